// round 10
// baseline (speedup 1.0000x reference)
#include <cuda_runtime.h>
#include <cstdint>
#include <cfloat>
#include <climits>

#define DIMD 64
#define NCODE 512
#define HW 4096
#define TPB 512
#define GRIDB 296                   // 2 blocks/SM single wave (148-152 SMs)
#define NVEC 131072
#define NUNITS (NVEC / 32)          // 4096 warp-units (32 vectors each)
#define CAP 6

// smem byte offsets
#define QW_OFF 0          // int8 codebook [513][64] (one zero pad row)
#define WN_OFF 33024      // ||w||^2 [512]
#define RED_OFF 35072     // reduce scratch [512 floats]
#define SMEM_TOTAL 37120

__device__ float g_psum[GRIDB];
__device__ int   g_ctr = 0;

extern __shared__ char smc[];

__global__ void __launch_bounds__(TPB, 2)
vq_dp4a_kernel(const float* __restrict__ in, const float* __restrict__ w,
               float* __restrict__ out_disc, float* __restrict__ out_q,
               float* __restrict__ out_loss, float inv_total)
{
    const int tid = threadIdx.x, bid = blockIdx.x;
    const int wid = tid >> 5, lane = tid & 31;
    char*  qw   = smc + QW_OFF;
    float* wn_s = (float*)(smc + WN_OFF);
    float* red  = (float*)(smc + RED_OFF);
    int*   redi = (int*)red;

    // ================= prologue =================
    float lm = 0.f;
    for (int i = tid; i < NCODE * DIMD; i += TPB) lm = fmaxf(lm, fabsf(w[i]));
    red[tid] = lm; __syncthreads();
#pragma unroll
    for (int s = TPB/2; s > 0; s >>= 1) {
        if (tid < s) red[tid] = fmaxf(red[tid], red[tid + s]);
        __syncthreads();
    }
    const float wmax = red[0];
    __syncthreads();

    // per-code (tid == code): wn + int8 quantize + sum|q|
    float wn_mine; int sabs_mine;
    {
        const float inv_w = 127.0f / wmax;
        const float4* src = (const float4*)(w + tid * DIMD);
        int4* qrow = (int4*)(qw + tid * 64);
        float s = 0.f; int sabs = 0;
#pragma unroll
        for (int i = 0; i < 16; i += 4) {
            int pk[4];
#pragma unroll
            for (int j = 0; j < 4; j++) {
                float4 v = src[i + j];
                s = fmaf(v.x, v.x, s); s = fmaf(v.y, v.y, s);
                s = fmaf(v.z, v.z, s); s = fmaf(v.w, v.w, s);
                int q0 = __float2int_rn(v.x * inv_w);
                int q1 = __float2int_rn(v.y * inv_w);
                int q2 = __float2int_rn(v.z * inv_w);
                int q3 = __float2int_rn(v.w * inv_w);
                sabs += abs(q0) + abs(q1) + abs(q2) + abs(q3);
                pk[j] = (q0 & 0xff) | ((q1 & 0xff) << 8)
                      | ((q2 & 0xff) << 16) | (q3 << 24);
            }
            qrow[i >> 2] = make_int4(pk[0], pk[1], pk[2], pk[3]);
        }
        wn_s[tid] = s; wn_mine = s; sabs_mine = sabs;
        if (tid < 4) ((int4*)(qw + NCODE * 64))[tid] = make_int4(0,0,0,0);
    }
    __syncthreads();
    redi[tid] = sabs_mine; __syncthreads();
#pragma unroll
    for (int s = TPB/2; s > 0; s >>= 1) {
        if (tid < s) redi[tid] = max(redi[tid], redi[tid + s]);
        __syncthreads();
    }
    const int W1max = redi[0]; __syncthreads();
    red[tid] = wn_mine; __syncthreads();
#pragma unroll
    for (int s = TPB/2; s > 0; s >>= 1) {
        if (tid < s) red[tid] = fminf(red[tid], red[tid + s]);
        __syncthreads();
    }
    const float wnmin = red[0]; __syncthreads();
    red[tid] = wn_mine; __syncthreads();
#pragma unroll
    for (int s = TPB/2; s > 0; s >>= 1) {
        if (tid < s) red[tid] = fmaxf(red[tid], red[tid + s]);
        __syncthreads();
    }
    const float wn_range = red[0] - wnmin;
    __syncthreads();

    // ================= one unit per warp =================
    float lsum = 0.f;
    const int u = bid + wid * GRIDB;
    if (u < NUNITS) {
        const int vec = u * 32 + lane;
        const int b = vec >> 12, hw = vec & (HW - 1);
        const float* xb = in + ((size_t)b << 18) + hw;

        // ---- pass over x: stats + quantize (x NOT kept in registers) ----
        float sxmax = 0.f, X1 = 0.f, A = 0.f;
        int qx[16];
#pragma unroll
        for (int i = 0; i < 16; i++) {
            float t0 = xb[(size_t)(4*i+0) << 12];
            float t1 = xb[(size_t)(4*i+1) << 12];
            float t2 = xb[(size_t)(4*i+2) << 12];
            float t3 = xb[(size_t)(4*i+3) << 12];
            sxmax = fmaxf(fmaxf(sxmax, fabsf(t0)), fmaxf(fabsf(t1),
                    fmaxf(fabsf(t2), fabsf(t3))));
            X1 += fabsf(t0) + fabsf(t1) + fabsf(t2) + fabsf(t3);
            A = fmaf(t0, t0, A); A = fmaf(t1, t1, A);
            A = fmaf(t2, t2, A); A = fmaf(t3, t3, A);
            qx[i] = i;  // placeholder, quantized below after inv_x known
        }
        {
            float inv_x = (sxmax > 0.f) ? 127.0f / sxmax : 0.f;
#pragma unroll
            for (int i = 0; i < 16; i++) {
                int q0 = __float2int_rn(xb[(size_t)(4*i+0) << 12] * inv_x);
                int q1 = __float2int_rn(xb[(size_t)(4*i+1) << 12] * inv_x);
                int q2 = __float2int_rn(xb[(size_t)(4*i+2) << 12] * inv_x);
                int q3 = __float2int_rn(xb[(size_t)(4*i+3) << 12] * inv_x);
                qx[i] = (q0 & 0xff) | ((q1 & 0xff) << 8)
                      | ((q2 & 0xff) << 16) | (q3 << 24);
            }
        }
        // rigorous integer margin (same bound as R7/R8, rel_err 0.0 pedigree)
        int M;
        {
            const float sx = sxmax * (1.0f / 127.0f);
            const float sw = wmax * (1.0f / 127.0f);
            float mf = (sxmax > 0.f)
                ? 1.02f * ((float)W1max + 32.0f + X1 * (127.0f / sxmax)
                           + 0.5f * wn_range / (sx * sw))
                : 2.1e9f;
            mf = fminf(mf, 2.1e9f);
            M = (int)ceilf(mf) + 2;
        }

        // ---- int8 scan over 512 codes ----
        int smax = INT_MIN / 2, thr = INT_MIN / 2;
        int cnt = 0, ovf = 0;
        int candK[CAP];                       // s*512 | code
        const int4* qr = (const int4*)qw;
#pragma unroll 2
        for (int code = 0; code < NCODE; code++) {
            int4 v0 = qr[code*4+0], v1 = qr[code*4+1];
            int4 v2 = qr[code*4+2], v3 = qr[code*4+3];
            int a0 = __dp4a(v0.x, qx[0], 0);
            int a1 = __dp4a(v0.y, qx[1], 0);
            int a2 = __dp4a(v0.z, qx[2], 0);
            int a3 = __dp4a(v0.w, qx[3], 0);
            a0 = __dp4a(v1.x, qx[4],  a0); a1 = __dp4a(v1.y, qx[5],  a1);
            a2 = __dp4a(v1.z, qx[6],  a2); a3 = __dp4a(v1.w, qx[7],  a3);
            a0 = __dp4a(v2.x, qx[8],  a0); a1 = __dp4a(v2.y, qx[9],  a1);
            a2 = __dp4a(v2.z, qx[10], a2); a3 = __dp4a(v2.w, qx[11], a3);
            a0 = __dp4a(v3.x, qx[12], a0); a1 = __dp4a(v3.y, qx[13], a1);
            a2 = __dp4a(v3.z, qx[14], a2); a3 = __dp4a(v3.w, qx[15], a3);
            int s = (a0 + a1) + (a2 + a3);
            if (s > thr) {                    // rare path
                if (s > smax) { smax = s; thr = smax - M; }
                if (cnt == CAP) {             // purge entries at/below threshold
                    long long tK = (long long)thr * 512 + 511;
                    int nc = 0;
#pragma unroll
                    for (int sl = 0; sl < CAP; sl++)
                        if ((long long)candK[sl] > tK) candK[nc++] = candK[sl];
                    cnt = nc;
                }
                if (cnt < CAP) candK[cnt++] = s * 512 + code;
                else ovf = 1;                 // sticky -> exact full rescan
            }
        }

        // ---- exact rescore (streamed x; same arithmetic as R7, rel_err 0.0) ----
        float bd = FLT_MAX; int bi = 0;
        const float4* wq = (const float4*)w;
        const long long fK = (long long)(smax - M) * 512;
        if (ovf) {
            for (int code = 0; code < NCODE; code++) {
                float s0 = 0.f, s1 = 0.f, s2 = 0.f, s3 = 0.f;
#pragma unroll
                for (int i = 0; i < 16; i++) {
                    float4 wv = __ldg(&wq[code * 16 + i]);
                    s0 = fmaf(xb[(size_t)(4*i+0) << 12], wv.x, s0);
                    s1 = fmaf(xb[(size_t)(4*i+1) << 12], wv.y, s1);
                    s2 = fmaf(xb[(size_t)(4*i+2) << 12], wv.z, s2);
                    s3 = fmaf(xb[(size_t)(4*i+3) << 12], wv.w, s3);
                }
                float dv = fmaf(-2.f, (s0 + s1) + (s2 + s3), A) + wn_s[code];
                if (dv < bd) { bd = dv; bi = code; }
            }
        } else {
            int live = 0, lastc = 0;
#pragma unroll
            for (int sl = 0; sl < CAP; sl++)
                if (sl < cnt && (long long)candK[sl] >= fK) {
                    live++; lastc = candK[sl] & 511;
                }
            if (live == 1) {                  // unique candidate: argmin proven
                bi = lastc;
            } else {
                // sort-free: candidates appended in ascending code order
                for (int e = 0; e < cnt; e++) {
                    if ((long long)candK[e] >= fK) {
                        int code = candK[e] & 511;
                        float s0 = 0.f, s1 = 0.f, s2 = 0.f, s3 = 0.f;
#pragma unroll
                        for (int i = 0; i < 16; i++) {
                            float4 wv = __ldg(&wq[code * 16 + i]);
                            s0 = fmaf(xb[(size_t)(4*i+0) << 12], wv.x, s0);
                            s1 = fmaf(xb[(size_t)(4*i+1) << 12], wv.y, s1);
                            s2 = fmaf(xb[(size_t)(4*i+2) << 12], wv.z, s2);
                            s3 = fmaf(xb[(size_t)(4*i+3) << 12], wv.w, s3);
                        }
                        float dv = fmaf(-2.f, (s0 + s1) + (s2 + s3), A) + wn_s[code];
                        if (dv < bd) { bd = dv; bi = code; }  // strict <: first-min
                    }
                }
            }
        }

        // ---- epilogue: streamed x (L1 hits), gathered w, coalesced stores ----
        out_disc[vec] = (float)bi;
        float* qb = out_q + ((size_t)b << 18) + hw;
#pragma unroll
        for (int i = 0; i < 16; i++) {
            float4 wv = __ldg(&wq[bi * 16 + i]);
            float x0 = xb[(size_t)(4*i+0) << 12];
            float x1 = xb[(size_t)(4*i+1) << 12];
            float x2 = xb[(size_t)(4*i+2) << 12];
            float x3 = xb[(size_t)(4*i+3) << 12];
            float d0 = wv.x - x0, d1 = wv.y - x1;
            float d2 = wv.z - x2, d3 = wv.w - x3;
            qb[(size_t)(4*i+0) << 12] = x0 + d0;
            qb[(size_t)(4*i+1) << 12] = x1 + d1;
            qb[(size_t)(4*i+2) << 12] = x2 + d2;
            qb[(size_t)(4*i+3) << 12] = x3 + d3;
            lsum = fmaf(d0, d0, lsum); lsum = fmaf(d1, d1, lsum);
            lsum = fmaf(d2, d2, lsum); lsum = fmaf(d3, d3, lsum);
        }
    }

    // ---- deterministic loss: block partial, last block finalizes ----
    __syncthreads();
    red[tid] = lsum; __syncthreads();
#pragma unroll
    for (int s = TPB/2; s > 0; s >>= 1) {
        if (tid < s) red[tid] += red[tid + s];
        __syncthreads();
    }
    if (tid == 0) {
        g_psum[bid] = red[0];
        __threadfence();
        int arrived = atomicAdd(&g_ctr, 1);
        if (arrived == GRIDB - 1) {           // sequential exact sum (fixed order)
            float s = 0.f;
            for (int i = 0; i < GRIDB; i++) s += g_psum[i];
            float m = s * inv_total;
            out_loss[0] = m + 0.25f * m;
            g_ctr = 0;                        // reset for next graph replay
            __threadfence();
        }
    }
}

extern "C" void kernel_launch(void* const* d_in, const int* in_sizes, int n_in,
                              void* d_out, int out_size)
{
    const float* in = (const float*)d_in[0];   // [32,64,64,64] fp32
    const float* w  = (const float*)d_in[1];   // [512,64] fp32
    const int n_elems = in_sizes[0];           // 8388608
    const int nvec    = n_elems / DIMD;        // 131072

    float* out      = (float*)d_out;
    float* out_disc = out;
    float* out_q    = out + nvec;
    float* out_loss = out + nvec + n_elems;

    static bool attr_set = false;
    if (!attr_set) {
        cudaFuncSetAttribute(vq_dp4a_kernel,
                             cudaFuncAttributeMaxDynamicSharedMemorySize, SMEM_TOTAL);
        attr_set = true;
    }
    vq_dp4a_kernel<<<GRIDB, TPB, SMEM_TOTAL>>>(in, w, out_disc, out_q,
                                               out_loss, 1.0f / (float)n_elems);
}

// round 11
// speedup vs baseline: 1.1953x; 1.1953x over previous
#include <cuda_runtime.h>
#include <cstdint>
#include <cfloat>
#include <climits>

#define DIMD 64
#define NCODE 512
#define HW 4096
#define TPB 256
#define GRIDB 444                  // 3 blocks/SM x 148 SMs, single wave
#define NVEC 131072
#define NUNITS (NVEC / 32)         // 4096 warp-units (32 vectors each)
#define CAP 8

// smem byte offsets
#define QW_OFF 0          // int8 codebook [513][64] (one zero pad row)
#define WN_OFF 33024      // ||w||^2 [512]
#define RED_OFF 35072     // reduce scratch [256 floats] + flag
#define SMEM_TOTAL 37120

__device__ float g_upsum[NUNITS];  // per-unit loss partials (unit-indexed: deterministic)
__device__ int   g_uctr = 0;       // unit work-stealing counter
__device__ int   g_ctr  = 0;       // block arrival counter

extern __shared__ char smc[];

__global__ void __launch_bounds__(TPB, 3)
vq_dp4a_kernel(const float* __restrict__ in, const float* __restrict__ w,
               float* __restrict__ out_disc, float* __restrict__ out_q,
               float* __restrict__ out_loss, float inv_total)
{
    const int tid = threadIdx.x;
    const int lane = tid & 31;
    char*  qw   = smc + QW_OFF;
    float* wn_s = (float*)(smc + WN_OFF);
    float* red  = (float*)(smc + RED_OFF);
    int*   redi = (int*)red;

    // ================= prologue (per block) =================
    float lm = 0.f;
    for (int i = tid; i < NCODE * DIMD; i += TPB) lm = fmaxf(lm, fabsf(w[i]));
    red[tid] = lm; __syncthreads();
#pragma unroll
    for (int s = TPB/2; s > 0; s >>= 1) {
        if (tid < s) red[tid] = fmaxf(red[tid], red[tid + s]);
        __syncthreads();
    }
    const float wmax = red[0];
    __syncthreads();

    // codes: each thread handles code tid and tid+256
    int   sabs_mine = 0;
    float wn_lo = 0.f, wn_hi = 0.f;
    {
        const float inv_w = 127.0f / wmax;
#pragma unroll
        for (int h = 0; h < 2; h++) {
            const int c = tid + h * 256;
            const float4* src = (const float4*)(w + c * DIMD);
            int4* qrow = (int4*)(qw + c * 64);
            float s = 0.f; int sabs = 0;
#pragma unroll
            for (int i = 0; i < 16; i += 4) {
                int pk[4];
#pragma unroll
                for (int j = 0; j < 4; j++) {
                    float4 v = src[i + j];
                    s = fmaf(v.x, v.x, s); s = fmaf(v.y, v.y, s);
                    s = fmaf(v.z, v.z, s); s = fmaf(v.w, v.w, s);
                    int q0 = __float2int_rn(v.x * inv_w);
                    int q1 = __float2int_rn(v.y * inv_w);
                    int q2 = __float2int_rn(v.z * inv_w);
                    int q3 = __float2int_rn(v.w * inv_w);
                    sabs += abs(q0) + abs(q1) + abs(q2) + abs(q3);
                    pk[j] = (q0 & 0xff) | ((q1 & 0xff) << 8)
                          | ((q2 & 0xff) << 16) | (q3 << 24);
                }
                qrow[i >> 2] = make_int4(pk[0], pk[1], pk[2], pk[3]);
            }
            wn_s[c] = s;
            if (h == 0) wn_lo = s; else wn_hi = s;
            sabs_mine = max(sabs_mine, sabs);
        }
        if (tid < 4) ((int4*)(qw + NCODE * 64))[tid] = make_int4(0,0,0,0);
    }
    __syncthreads();
    redi[tid] = sabs_mine; __syncthreads();
#pragma unroll
    for (int s = TPB/2; s > 0; s >>= 1) {
        if (tid < s) redi[tid] = max(redi[tid], redi[tid + s]);
        __syncthreads();
    }
    const int W1max = redi[0]; __syncthreads();
    red[tid] = fminf(wn_lo, wn_hi); __syncthreads();
#pragma unroll
    for (int s = TPB/2; s > 0; s >>= 1) {
        if (tid < s) red[tid] = fminf(red[tid], red[tid + s]);
        __syncthreads();
    }
    const float wnmin = red[0]; __syncthreads();
    red[tid] = fmaxf(wn_lo, wn_hi); __syncthreads();
#pragma unroll
    for (int s = TPB/2; s > 0; s >>= 1) {
        if (tid < s) red[tid] = fmaxf(red[tid], red[tid + s]);
        __syncthreads();
    }
    const float wn_range = red[0] - wnmin;
    __syncthreads();

    // ================= persistent warp loop: steal units =================
    const int4* qr = (const int4*)qw;
    const float4* wq = (const float4*)w;

    for (;;) {
        int myu = 0;
        if (lane == 0) myu = atomicAdd(&g_uctr, 1);
        myu = __shfl_sync(0xffffffffu, myu, 0);
        if (myu >= NUNITS) break;

        const int vec = myu * 32 + lane;
        const int b = vec >> 12, hw = vec & (HW - 1);
        const float* xb = in + (b << 18) + hw;

        // ---- pass 1: stats (x not kept) ----
        float sxmax = 0.f, X1 = 0.f, A = 0.f;
#pragma unroll
        for (int d = 0; d < DIMD; d++) {
            float t = xb[d << 12];
            sxmax = fmaxf(sxmax, fabsf(t));
            X1 += fabsf(t);
            A = fmaf(t, t, A);
        }
        // ---- pass 2: quantize (L1 hits) ----
        int qx[16];
        {
            float inv_x = (sxmax > 0.f) ? 127.0f / sxmax : 0.f;
#pragma unroll
            for (int i = 0; i < 16; i++) {
                int q0 = __float2int_rn(xb[(4*i+0) << 12] * inv_x);
                int q1 = __float2int_rn(xb[(4*i+1) << 12] * inv_x);
                int q2 = __float2int_rn(xb[(4*i+2) << 12] * inv_x);
                int q3 = __float2int_rn(xb[(4*i+3) << 12] * inv_x);
                qx[i] = (q0 & 0xff) | ((q1 & 0xff) << 8)
                      | ((q2 & 0xff) << 16) | (q3 << 24);
            }
        }
        // rigorous integer margin (R7/R8 pedigree, rel_err 0.0)
        int M;
        {
            const float sx = sxmax * (1.0f / 127.0f);
            const float sw = wmax * (1.0f / 127.0f);
            float mf = (sxmax > 0.f)
                ? 1.02f * ((float)W1max + 32.0f + X1 * (127.0f / sxmax)
                           + 0.5f * wn_range / (sx * sw))
                : 2.1e9f;
            mf = fminf(mf, 2.1e9f);
            M = (int)ceilf(mf) + 2;
        }

        // ---- int8 scan; candidate slots are STATIC-indexed (registers) ----
        int smax = INT_MIN / 2, thr = INT_MIN / 2, ovf = 0;
        int candS[CAP], candC[CAP];
#pragma unroll
        for (int sl = 0; sl < CAP; sl++) { candS[sl] = INT_MIN / 2; candC[sl] = 0; }

#pragma unroll 2
        for (int code = 0; code < NCODE; code++) {
            int4 v0 = qr[code*4+0], v1 = qr[code*4+1];
            int4 v2 = qr[code*4+2], v3 = qr[code*4+3];
            int a0 = __dp4a(v0.x, qx[0], 0);
            int a1 = __dp4a(v0.y, qx[1], 0);
            int a2 = __dp4a(v0.z, qx[2], 0);
            int a3 = __dp4a(v0.w, qx[3], 0);
            a0 = __dp4a(v1.x, qx[4],  a0); a1 = __dp4a(v1.y, qx[5],  a1);
            a2 = __dp4a(v1.z, qx[6],  a2); a3 = __dp4a(v1.w, qx[7],  a3);
            a0 = __dp4a(v2.x, qx[8],  a0); a1 = __dp4a(v2.y, qx[9],  a1);
            a2 = __dp4a(v2.z, qx[10], a2); a3 = __dp4a(v2.w, qx[11], a3);
            a0 = __dp4a(v3.x, qx[12], a0); a1 = __dp4a(v3.y, qx[13], a1);
            a2 = __dp4a(v3.z, qx[14], a2); a3 = __dp4a(v3.w, qx[15], a3);
            int s = (a0 + a1) + (a2 + a3);
            if (s > thr) {                 // rare path
                if (s > smax) { smax = s; thr = s - M; }
                bool placed = false;
#pragma unroll
                for (int sl = 0; sl < CAP; sl++)
                    if (!placed && candS[sl] <= thr) {   // dead slot: reuse
                        candS[sl] = s; candC[sl] = code; placed = true;
                    }
                if (!placed) ovf = 1;      // sticky -> exact full rescan
            }
        }

        // ---- exact rescore (streamed x/w; R3-identical arithmetic) ----
        float bd = FLT_MAX; int bi = 1023;
        if (ovf) {
            for (int code = 0; code < NCODE; code++) {
                float s0 = 0.f, s1 = 0.f, s2 = 0.f, s3 = 0.f;
#pragma unroll
                for (int i = 0; i < 16; i++) {
                    float4 wv = __ldg(&wq[code * 16 + i]);
                    s0 = fmaf(xb[(4*i+0) << 12], wv.x, s0);
                    s1 = fmaf(xb[(4*i+1) << 12], wv.y, s1);
                    s2 = fmaf(xb[(4*i+2) << 12], wv.z, s2);
                    s3 = fmaf(xb[(4*i+3) << 12], wv.w, s3);
                }
                float dv = fmaf(-2.f, (s0 + s1) + (s2 + s3), A) + wn_s[code];
                if (dv < bd) { bd = dv; bi = code; }   // ascending: first-min
            }
        } else {
            int live = 0, onlyc = 0;
#pragma unroll
            for (int sl = 0; sl < CAP; sl++)
                if (candS[sl] > thr) { live++; onlyc = candC[sl]; }
            if (live == 1) {               // unique candidate: argmin proven
                bi = onlyc;
            } else {
#pragma unroll
                for (int sl = 0; sl < CAP; sl++) {
                    if (candS[sl] > thr) {
                        const int code = candC[sl];
                        float s0 = 0.f, s1 = 0.f, s2 = 0.f, s3 = 0.f;
#pragma unroll
                        for (int i = 0; i < 16; i++) {
                            float4 wv = __ldg(&wq[code * 16 + i]);
                            s0 = fmaf(xb[(4*i+0) << 12], wv.x, s0);
                            s1 = fmaf(xb[(4*i+1) << 12], wv.y, s1);
                            s2 = fmaf(xb[(4*i+2) << 12], wv.z, s2);
                            s3 = fmaf(xb[(4*i+3) << 12], wv.w, s3);
                        }
                        float dv = fmaf(-2.f, (s0 + s1) + (s2 + s3), A) + wn_s[code];
                        // slots unordered: explicit lowest-index tie-break
                        if (dv < bd || (dv == bd && code < bi)) { bd = dv; bi = code; }
                    }
                }
            }
        }

        // ---- epilogue: streamed x, gathered w, coalesced stores ----
        out_disc[vec] = (float)bi;
        float* qb = out_q + (b << 18) + hw;
        float lsum = 0.f;
#pragma unroll
        for (int i = 0; i < 16; i++) {
            float4 wv = __ldg(&wq[bi * 16 + i]);
            float x0 = xb[(4*i+0) << 12];
            float x1 = xb[(4*i+1) << 12];
            float x2 = xb[(4*i+2) << 12];
            float x3 = xb[(4*i+3) << 12];
            float d0 = wv.x - x0, d1 = wv.y - x1;
            float d2 = wv.z - x2, d3 = wv.w - x3;
            qb[(4*i+0) << 12] = x0 + d0;
            qb[(4*i+1) << 12] = x1 + d1;
            qb[(4*i+2) << 12] = x2 + d2;
            qb[(4*i+3) << 12] = x3 + d3;
            lsum = fmaf(d0, d0, lsum); lsum = fmaf(d1, d1, lsum);
            lsum = fmaf(d2, d2, lsum); lsum = fmaf(d3, d3, lsum);
        }
        // fixed-order warp reduction -> unit-indexed partial (deterministic)
#pragma unroll
        for (int off = 16; off > 0; off >>= 1)
            lsum += __shfl_xor_sync(0xffffffffu, lsum, off);
        if (lane == 0) g_upsum[myu] = lsum;
    }

    // ================= finalize: last block reduces in fixed order =========
    __syncthreads();
    if (tid == 0) {
        __threadfence();
        int a = atomicAdd(&g_ctr, 1);
        redi[0] = (a == GRIDB - 1) ? 1 : 0;
    }
    __syncthreads();
    if (redi[0]) {
        __threadfence();
        float s = 0.f;
#pragma unroll
        for (int k = 0; k < NUNITS / TPB; k++)   // fixed mapping + order
            s += g_upsum[tid * (NUNITS / TPB) + k];
        __syncthreads();
        red[tid] = s; __syncthreads();
#pragma unroll
        for (int st = TPB/2; st > 0; st >>= 1) {
            if (tid < st) red[tid] += red[tid + st];
            __syncthreads();
        }
        if (tid == 0) {
            float m = red[0] * inv_total;
            out_loss[0] = m + 0.25f * m;
            g_ctr = 0; g_uctr = 0;              // reset for next graph replay
            __threadfence();
        }
    }
}

extern "C" void kernel_launch(void* const* d_in, const int* in_sizes, int n_in,
                              void* d_out, int out_size)
{
    const float* in = (const float*)d_in[0];   // [32,64,64,64] fp32
    const float* w  = (const float*)d_in[1];   // [512,64] fp32
    const int n_elems = in_sizes[0];           // 8388608
    const int nvec    = n_elems / DIMD;        // 131072

    float* out      = (float*)d_out;
    float* out_disc = out;
    float* out_q    = out + nvec;
    float* out_loss = out + nvec + n_elems;

    static bool attr_set = false;
    if (!attr_set) {
        cudaFuncSetAttribute(vq_dp4a_kernel,
                             cudaFuncAttributeMaxDynamicSharedMemorySize, SMEM_TOTAL);
        attr_set = true;
    }
    vq_dp4a_kernel<<<GRIDB, TPB, SMEM_TOTAL>>>(in, w, out_disc, out_q,
                                               out_loss, 1.0f / (float)n_elems);
}

// round 16
// speedup vs baseline: 1.3102x; 1.0961x over previous
#include <cuda_runtime.h>
#include <cstdint>
#include <cfloat>
#include <climits>

#define DIMD 64
#define NCODE 512
#define HW 4096
#define TPB 256                    // 8 warps/block
#define GRIDB 148
#define NVEC 131072
#define NPAIR 2048                 // 4096 units / 2 per warp
#define NWARPS (GRIDB * (TPB/32))  // 1184
#define CAP 8

// smem byte offsets
#define QW_OFF 0          // int8 codebook [513][64] (one zero pad row)
#define WN_OFF 33024      // ||w||^2 [512]
#define RED_OFF 35072     // reduce scratch [8 floats]
#define SMEM_TOTAL 35200

__device__ float g_psum[GRIDB];
__device__ int   g_ctr = 0;

extern __shared__ char smc[];

__device__ __forceinline__ float blk_maxf(float v, float* red, int wid, int lane) {
#pragma unroll
    for (int o = 16; o > 0; o >>= 1) v = fmaxf(v, __shfl_xor_sync(~0u, v, o));
    if (lane == 0) red[wid] = v;
    __syncthreads();
    if (threadIdx.x == 0) {
        float m = red[0];
#pragma unroll
        for (int i = 1; i < TPB / 32; i++) m = fmaxf(m, red[i]);
        red[0] = m;
    }
    __syncthreads();
    float r = red[0];
    __syncthreads();
    return r;
}
__device__ __forceinline__ float blk_minf(float v, float* red, int wid, int lane) {
#pragma unroll
    for (int o = 16; o > 0; o >>= 1) v = fminf(v, __shfl_xor_sync(~0u, v, o));
    if (lane == 0) red[wid] = v;
    __syncthreads();
    if (threadIdx.x == 0) {
        float m = red[0];
#pragma unroll
        for (int i = 1; i < TPB / 32; i++) m = fminf(m, red[i]);
        red[0] = m;
    }
    __syncthreads();
    float r = red[0];
    __syncthreads();
    return r;
}

// Exact distance: bitwise-identical to R3/R8 arithmetic (rel_err == 0.0).
__device__ __forceinline__ float exact_dist(const float* __restrict__ xb,
                                            float A, const float4* __restrict__ wq,
                                            const float* wn_s, int code) {
    float s0 = 0.f, s1 = 0.f, s2 = 0.f, s3 = 0.f;
#pragma unroll
    for (int i = 0; i < 16; i++) {
        float4 wv = __ldg(&wq[code * 16 + i]);
        s0 = fmaf(xb[(4*i+0) << 12], wv.x, s0);
        s1 = fmaf(xb[(4*i+1) << 12], wv.y, s1);
        s2 = fmaf(xb[(4*i+2) << 12], wv.z, s2);
        s3 = fmaf(xb[(4*i+3) << 12], wv.w, s3);
    }
    return fmaf(-2.f, (s0 + s1) + (s2 + s3), A) + wn_s[code];
}

// candidate select + exact rescore for one vector (R8-proven semantics)
__device__ __forceinline__ int pick_code(const float* __restrict__ xb, float A,
                                         const float4* __restrict__ wq,
                                         const float* wn_s,
                                         const int* candS, const int* candC,
                                         int cnt, int ovf, int fthr) {
    float bd = FLT_MAX; int bi = 0;
    if (ovf) {
        for (int code = 0; code < NCODE; code++) {
            float dv = exact_dist(xb, A, wq, wn_s, code);
            if (dv < bd) { bd = dv; bi = code; }       // ascending: first-min
        }
        return bi;
    }
    int live = 0, onlyc = 0;
    for (int e = 0; e < cnt; e++)
        if (candS[e] >= fthr) { live++; onlyc = candC[e]; }
    if (live == 1) return onlyc;                       // argmin proven
    for (int e = 0; e < cnt; e++) {                    // order-preserved: ascending
        if (candS[e] >= fthr) {
            float dv = exact_dist(xb, A, wq, wn_s, candC[e]);
            if (dv < bd) { bd = dv; bi = candC[e]; }   // strict <: first-min ties
        }
    }
    return bi;
}

__global__ void vq_dp4a_kernel(const float* __restrict__ in,
                               const float* __restrict__ w,
                               float* __restrict__ out_disc,
                               float* __restrict__ out_q,
                               float* __restrict__ out_loss, float inv_total)
{
    const int tid = threadIdx.x, bid = blockIdx.x;
    const int wid = tid >> 5, lane = tid & 31;
    char*  qw   = smc + QW_OFF;
    float* wn_s = (float*)(smc + WN_OFF);
    float* red  = (float*)(smc + RED_OFF);

    // ================= prologue =================
    float lm = 0.f;
    for (int i = tid; i < NCODE * DIMD; i += TPB) lm = fmaxf(lm, fabsf(w[i]));
    const float wmax = blk_maxf(lm, red, wid, lane);

    // codebook quantize: codes tid, tid+256
    float wn_min_l = FLT_MAX, wn_max_l = -FLT_MAX; int sabs_l = 0;
    {
        const float inv_w = 127.0f / wmax;
#pragma unroll
        for (int h = 0; h < 2; h++) {
            const int c = tid + h * 256;
            const float4* src = (const float4*)(w + c * DIMD);
            int4* qrow = (int4*)(qw + c * 64);
            float s = 0.f; int sabs = 0;
#pragma unroll
            for (int i = 0; i < 16; i += 4) {
                int pk[4];
#pragma unroll
                for (int j = 0; j < 4; j++) {
                    float4 v = src[i + j];
                    s = fmaf(v.x, v.x, s); s = fmaf(v.y, v.y, s);
                    s = fmaf(v.z, v.z, s); s = fmaf(v.w, v.w, s);
                    int q0 = __float2int_rn(v.x * inv_w);
                    int q1 = __float2int_rn(v.y * inv_w);
                    int q2 = __float2int_rn(v.z * inv_w);
                    int q3 = __float2int_rn(v.w * inv_w);
                    sabs += abs(q0) + abs(q1) + abs(q2) + abs(q3);
                    pk[j] = (q0 & 0xff) | ((q1 & 0xff) << 8)
                          | ((q2 & 0xff) << 16) | (q3 << 24);
                }
                qrow[i >> 2] = make_int4(pk[0], pk[1], pk[2], pk[3]);
            }
            wn_s[c] = s;
            wn_min_l = fminf(wn_min_l, s);
            wn_max_l = fmaxf(wn_max_l, s);
            sabs_l = max(sabs_l, sabs);
        }
        if (tid < 4) ((int4*)(qw + NCODE * 64))[tid] = make_int4(0,0,0,0);
    }
    __syncthreads();
    const int   W1max    = (int)blk_maxf((float)sabs_l, red, wid, lane);
    const float wnmin    = blk_minf(wn_min_l, red, wid, lane);
    const float wn_range = blk_maxf(wn_max_l, red, wid, lane) - wnmin;

    // ================= unit-PAIR loop (1-2 pairs per warp) =================
    float lsum = 0.f;
    const int gw = bid * (TPB / 32) + wid;     // global warp id
    for (int g = gw; g < NPAIR; g += NWARPS) {
        const int vec0 = g * 64 + lane;        // unit 2g
        const int b = vec0 >> 12, hw = vec0 & (HW - 1);
        const float* xb0 = in + (b << 18) + hw;
        const float* xb1 = xb0 + 32;           // unit 2g+1 (same b, never wraps)

        // ---- stats (x streamed, not kept) ----
        float sx0 = 0.f, X10 = 0.f, A0 = 0.f;
        float sx1 = 0.f, X11 = 0.f, A1 = 0.f;
#pragma unroll
        for (int d = 0; d < DIMD; d++) {
            float t0 = xb0[d << 12], t1 = xb1[d << 12];
            sx0 = fmaxf(sx0, fabsf(t0)); X10 += fabsf(t0); A0 = fmaf(t0, t0, A0);
            sx1 = fmaxf(sx1, fabsf(t1)); X11 += fabsf(t1); A1 = fmaf(t1, t1, A1);
        }
        // ---- quantize both (reloads are L1 hits) ----
        int qx0[16], qx1[16];
        {
            float ia = (sx0 > 0.f) ? 127.0f / sx0 : 0.f;
            float ib = (sx1 > 0.f) ? 127.0f / sx1 : 0.f;
#pragma unroll
            for (int i = 0; i < 16; i++) {
                int a0 = __float2int_rn(xb0[(4*i+0) << 12] * ia);
                int a1 = __float2int_rn(xb0[(4*i+1) << 12] * ia);
                int a2 = __float2int_rn(xb0[(4*i+2) << 12] * ia);
                int a3 = __float2int_rn(xb0[(4*i+3) << 12] * ia);
                qx0[i] = (a0 & 0xff) | ((a1 & 0xff) << 8)
                       | ((a2 & 0xff) << 16) | (a3 << 24);
                int b0 = __float2int_rn(xb1[(4*i+0) << 12] * ib);
                int b1 = __float2int_rn(xb1[(4*i+1) << 12] * ib);
                int b2 = __float2int_rn(xb1[(4*i+2) << 12] * ib);
                int b3 = __float2int_rn(xb1[(4*i+3) << 12] * ib);
                qx1[i] = (b0 & 0xff) | ((b1 & 0xff) << 8)
                       | ((b2 & 0xff) << 16) | (b3 << 24);
            }
        }
        // rigorous integer margins (R7/R8 pedigree)
        int M0, M1;
        {
            const float sw = wmax * (1.0f / 127.0f);
            float mf0 = (sx0 > 0.f)
                ? 1.02f * ((float)W1max + 32.0f + X10 * (127.0f / sx0)
                           + 0.5f * wn_range / ((sx0 / 127.0f) * sw)) : 2.1e9f;
            float mf1 = (sx1 > 0.f)
                ? 1.02f * ((float)W1max + 32.0f + X11 * (127.0f / sx1)
                           + 0.5f * wn_range / ((sx1 / 127.0f) * sw)) : 2.1e9f;
            M0 = (int)ceilf(fminf(mf0, 2.1e9f)) + 2;
            M1 = (int)ceilf(fminf(mf1, 2.1e9f)) + 2;
        }

        // ---- int8 scan: both vectors per code row (8 dp4a chains) ----
        int smax0 = INT_MIN/2, thr0 = INT_MIN/2, cnt0 = 0, ovf0 = 0;
        int smax1 = INT_MIN/2, thr1 = INT_MIN/2, cnt1 = 0, ovf1 = 0;
        int c0S[CAP], c0C[CAP], c1S[CAP], c1C[CAP];
        const int4* qr = (const int4*)qw;
#pragma unroll 2
        for (int code = 0; code < NCODE; code++) {
            int4 v0 = qr[code*4+0], v1 = qr[code*4+1];
            int4 v2 = qr[code*4+2], v3 = qr[code*4+3];
            int a0 = __dp4a(v0.x, qx0[0], 0);
            int a1 = __dp4a(v0.y, qx0[1], 0);
            int a2 = __dp4a(v0.z, qx0[2], 0);
            int a3 = __dp4a(v0.w, qx0[3], 0);
            int b0 = __dp4a(v0.x, qx1[0], 0);
            int b1 = __dp4a(v0.y, qx1[1], 0);
            int b2 = __dp4a(v0.z, qx1[2], 0);
            int b3 = __dp4a(v0.w, qx1[3], 0);
            a0 = __dp4a(v1.x, qx0[4],  a0); a1 = __dp4a(v1.y, qx0[5],  a1);
            a2 = __dp4a(v1.z, qx0[6],  a2); a3 = __dp4a(v1.w, qx0[7],  a3);
            b0 = __dp4a(v1.x, qx1[4],  b0); b1 = __dp4a(v1.y, qx1[5],  b1);
            b2 = __dp4a(v1.z, qx1[6],  b2); b3 = __dp4a(v1.w, qx1[7],  b3);
            a0 = __dp4a(v2.x, qx0[8],  a0); a1 = __dp4a(v2.y, qx0[9],  a1);
            a2 = __dp4a(v2.z, qx0[10], a2); a3 = __dp4a(v2.w, qx0[11], a3);
            b0 = __dp4a(v2.x, qx1[8],  b0); b1 = __dp4a(v2.y, qx1[9],  b1);
            b2 = __dp4a(v2.z, qx1[10], b2); b3 = __dp4a(v2.w, qx1[11], b3);
            a0 = __dp4a(v3.x, qx0[12], a0); a1 = __dp4a(v3.y, qx0[13], a1);
            a2 = __dp4a(v3.z, qx0[14], a2); a3 = __dp4a(v3.w, qx0[15], a3);
            b0 = __dp4a(v3.x, qx1[12], b0); b1 = __dp4a(v3.y, qx1[13], b1);
            b2 = __dp4a(v3.z, qx1[14], b2); b3 = __dp4a(v3.w, qx1[15], b3);
            int sa = (a0 + a1) + (a2 + a3);
            int sb = (b0 + b1) + (b2 + b3);
            if (sa > thr0) {                   // rare path, order-preserving
                if (sa > smax0) { smax0 = sa; thr0 = sa - M0; }
                if (cnt0 == CAP) {
                    int nc = 0;
                    for (int sl = 0; sl < CAP; sl++)
                        if (c0S[sl] > thr0) { c0S[nc] = c0S[sl]; c0C[nc] = c0C[sl]; nc++; }
                    cnt0 = nc;
                }
                if (cnt0 < CAP) { c0S[cnt0] = sa; c0C[cnt0] = code; cnt0++; }
                else ovf0 = 1;
            }
            if (sb > thr1) {
                if (sb > smax1) { smax1 = sb; thr1 = sb - M1; }
                if (cnt1 == CAP) {
                    int nc = 0;
                    for (int sl = 0; sl < CAP; sl++)
                        if (c1S[sl] > thr1) { c1S[nc] = c1S[sl]; c1C[nc] = c1C[sl]; nc++; }
                    cnt1 = nc;
                }
                if (cnt1 < CAP) { c1S[cnt1] = sb; c1C[cnt1] = code; cnt1++; }
                else ovf1 = 1;
            }
        }

        // ---- rescore + epilogue ----
        const float4* wq = (const float4*)w;
        const int bi0 = pick_code(xb0, A0, wq, wn_s, c0S, c0C, cnt0, ovf0, smax0 - M0);
        const int bi1 = pick_code(xb1, A1, wq, wn_s, c1S, c1C, cnt1, ovf1, smax1 - M1);

        out_disc[vec0]      = (float)bi0;
        out_disc[vec0 + 32] = (float)bi1;
        float* qb0 = out_q + (b << 18) + hw;
        float* qb1 = qb0 + 32;
#pragma unroll
        for (int i = 0; i < 16; i++) {
            float4 w0 = __ldg(&wq[bi0 * 16 + i]);
            float4 w1 = __ldg(&wq[bi1 * 16 + i]);
#pragma unroll
            for (int j = 0; j < 4; j++) {
                float wc0 = j == 0 ? w0.x : j == 1 ? w0.y : j == 2 ? w0.z : w0.w;
                float wc1 = j == 0 ? w1.x : j == 1 ? w1.y : j == 2 ? w1.z : w1.w;
                int d = 4 * i + j;
                float x0 = xb0[d << 12], x1 = xb1[d << 12];
                float d0 = wc0 - x0, d1 = wc1 - x1;
                qb0[d << 12] = x0 + d0;
                qb1[d << 12] = x1 + d1;
                lsum = fmaf(d0, d0, lsum);
                lsum = fmaf(d1, d1, lsum);
            }
        }
    }

    // ---- deterministic loss: warp reduce -> block serial -> last block ----
#pragma unroll
    for (int o = 16; o > 0; o >>= 1) lsum += __shfl_xor_sync(~0u, lsum, o);
    __syncthreads();
    if (lane == 0) red[wid] = lsum;
    __syncthreads();
    if (tid == 0) {
        float s = 0.f;
#pragma unroll
        for (int i = 0; i < TPB / 32; i++) s += red[i];
        g_psum[bid] = s;
        __threadfence();
        int a = atomicAdd(&g_ctr, 1);
        if (a == GRIDB - 1) {                  // fixed-order exact final sum
            float t = 0.f;
            for (int i = 0; i < GRIDB; i++) t += g_psum[i];
            float m = t * inv_total;
            out_loss[0] = m + 0.25f * m;
            g_ctr = 0;                         // reset for next graph replay
            __threadfence();
        }
    }
}

extern "C" void kernel_launch(void* const* d_in, const int* in_sizes, int n_in,
                              void* d_out, int out_size)
{
    const float* in = (const float*)d_in[0];   // [32,64,64,64] fp32
    const float* w  = (const float*)d_in[1];   // [512,64] fp32
    const int n_elems = in_sizes[0];           // 8388608
    const int nvec    = n_elems / DIMD;        // 131072

    float* out      = (float*)d_out;
    float* out_disc = out;
    float* out_q    = out + nvec;
    float* out_loss = out + nvec + n_elems;

    static bool attr_set = false;
    if (!attr_set) {
        cudaFuncSetAttribute(vq_dp4a_kernel,
                             cudaFuncAttributeMaxDynamicSharedMemorySize, SMEM_TOTAL);
        attr_set = true;
    }
    vq_dp4a_kernel<<<GRIDB, TPB, SMEM_TOTAL>>>(in, w, out_disc, out_q,
                                               out_loss, 1.0f / (float)n_elems);
}

// round 17
// speedup vs baseline: 2.3033x; 1.7579x over previous
#include <cuda_runtime.h>
#include <cstdint>
#include <cfloat>
#include <climits>

#define DIMD 64
#define NCODE 512
#define HW 4096
#define TPB 448                     // 14 warps -> reg ceiling 146 (prefetch fits)
#define GRIDB 148
#define NVEC 131072
#define NUNITS (NVEC / 32)          // 4096 warp-units
#define NWARPS (GRIDB * (TPB / 32)) // 2072
#define CAP 16

// smem byte offsets
#define QW_OFF 0          // int8 codebook [513][64] (one zero pad row for prefetch)
#define WN_OFF 33024      // ||w||^2 [512]
#define RED_OFF 35072     // reduce scratch [14 floats]
#define SMEM_TOTAL 35200

__device__ float g_psum[GRIDB];
__device__ int   g_ctr = 0;

extern __shared__ char smc[];

__device__ __forceinline__ float blk_maxf(float v, float* red, int wid, int lane) {
#pragma unroll
    for (int o = 16; o > 0; o >>= 1) v = fmaxf(v, __shfl_xor_sync(~0u, v, o));
    if (lane == 0) red[wid] = v;
    __syncthreads();
    if (threadIdx.x == 0) {
        float m = red[0];
#pragma unroll
        for (int i = 1; i < TPB / 32; i++) m = fmaxf(m, red[i]);
        red[0] = m;
    }
    __syncthreads();
    float r = red[0];
    __syncthreads();
    return r;
}
__device__ __forceinline__ float blk_minf(float v, float* red, int wid, int lane) {
#pragma unroll
    for (int o = 16; o > 0; o >>= 1) v = fminf(v, __shfl_xor_sync(~0u, v, o));
    if (lane == 0) red[wid] = v;
    __syncthreads();
    if (threadIdx.x == 0) {
        float m = red[0];
#pragma unroll
        for (int i = 1; i < TPB / 32; i++) m = fminf(m, red[i]);
        red[0] = m;
    }
    __syncthreads();
    float r = red[0];
    __syncthreads();
    return r;
}

// Exact distance: bitwise-identical to R3/R8 arithmetic (rel_err == 0.0).
__device__ __forceinline__ float exact_dist(const float* __restrict__ xb,
                                            float A, const float4* __restrict__ wq,
                                            const float* wn_s, int code) {
    float s0 = 0.f, s1 = 0.f, s2 = 0.f, s3 = 0.f;
#pragma unroll
    for (int i = 0; i < 16; i++) {
        float4 wv = __ldg(&wq[code * 16 + i]);
        s0 = fmaf(xb[(4*i+0) << 12], wv.x, s0);
        s1 = fmaf(xb[(4*i+1) << 12], wv.y, s1);
        s2 = fmaf(xb[(4*i+2) << 12], wv.z, s2);
        s3 = fmaf(xb[(4*i+3) << 12], wv.w, s3);
    }
    return fmaf(-2.f, (s0 + s1) + (s2 + s3), A) + wn_s[code];
}

__global__ void vq_dp4a_kernel(const float* __restrict__ in,
                               const float* __restrict__ w,
                               float* __restrict__ out_disc,
                               float* __restrict__ out_q,
                               float* __restrict__ out_loss, float inv_total)
{
    const int tid = threadIdx.x, bid = blockIdx.x;
    const int wid = tid >> 5, lane = tid & 31;
    char*  qw   = smc + QW_OFF;
    float* wn_s = (float*)(smc + WN_OFF);
    float* red  = (float*)(smc + RED_OFF);

    // ================= prologue (R8-identical math) =================
    float lm = 0.f;
    for (int i = tid; i < NCODE * DIMD; i += TPB) lm = fmaxf(lm, fabsf(w[i]));
    const float wmax = blk_maxf(lm, red, wid, lane);

    float wn_min_l = FLT_MAX, wn_max_l = -FLT_MAX; int sabs_l = 0;
    {
        const float inv_w = 127.0f / wmax;
        for (int c = tid; c < NCODE; c += TPB) {
            const float4* src = (const float4*)(w + c * DIMD);
            int4* qrow = (int4*)(qw + c * 64);
            float s = 0.f; int sabs = 0;
#pragma unroll
            for (int i = 0; i < 16; i += 4) {
                int pk[4];
#pragma unroll
                for (int j = 0; j < 4; j++) {
                    float4 v = src[i + j];
                    s = fmaf(v.x, v.x, s); s = fmaf(v.y, v.y, s);
                    s = fmaf(v.z, v.z, s); s = fmaf(v.w, v.w, s);
                    int q0 = __float2int_rn(v.x * inv_w);
                    int q1 = __float2int_rn(v.y * inv_w);
                    int q2 = __float2int_rn(v.z * inv_w);
                    int q3 = __float2int_rn(v.w * inv_w);
                    sabs += abs(q0) + abs(q1) + abs(q2) + abs(q3);
                    pk[j] = (q0 & 0xff) | ((q1 & 0xff) << 8)
                          | ((q2 & 0xff) << 16) | (q3 << 24);
                }
                qrow[i >> 2] = make_int4(pk[0], pk[1], pk[2], pk[3]);
            }
            wn_s[c] = s;
            wn_min_l = fminf(wn_min_l, s);
            wn_max_l = fmaxf(wn_max_l, s);
            sabs_l = max(sabs_l, sabs);
        }
        if (tid < 4) ((int4*)(qw + NCODE * 64))[tid] = make_int4(0,0,0,0); // pad row
    }
    __syncthreads();
    const int   W1max    = (int)blk_maxf((float)sabs_l, red, wid, lane);
    const float wnmin    = blk_minf(wn_min_l, red, wid, lane);
    const float wn_range = blk_maxf(wn_max_l, red, wid, lane) - wnmin;

    // ================= main loop: <=2 units per warp =================
    float lsum = 0.f;
    const int gw = bid * (TPB / 32) + wid;
    for (int u = gw; u < NUNITS; u += NWARPS) {
        const int vec = u * 32 + lane;
        const int b = vec >> 12, hw = vec & (HW - 1);
        const float* xb = in + (b << 18) + hw;

        // ---- stats pass (x streamed) ----
        float sxmax = 0.f, X1 = 0.f, A = 0.f;
#pragma unroll
        for (int d = 0; d < DIMD; d++) {
            float t = xb[d << 12];
            sxmax = fmaxf(sxmax, fabsf(t));
            X1 += fabsf(t);
            A = fmaf(t, t, A);
        }
        // ---- quantize pass (L1 hits) ----
        int qx[16];
        {
            float inv_x = (sxmax > 0.f) ? 127.0f / sxmax : 0.f;
#pragma unroll
            for (int i = 0; i < 16; i++) {
                int q0 = __float2int_rn(xb[(4*i+0) << 12] * inv_x);
                int q1 = __float2int_rn(xb[(4*i+1) << 12] * inv_x);
                int q2 = __float2int_rn(xb[(4*i+2) << 12] * inv_x);
                int q3 = __float2int_rn(xb[(4*i+3) << 12] * inv_x);
                qx[i] = (q0 & 0xff) | ((q1 & 0xff) << 8)
                      | ((q2 & 0xff) << 16) | (q3 << 24);
            }
        }
        // rigorous integer margin (R7/R8 pedigree, rel_err 0.0)
        int M;
        {
            const float sx = sxmax * (1.0f / 127.0f);
            const float sw = wmax * (1.0f / 127.0f);
            float mf = (sxmax > 0.f)
                ? 1.02f * ((float)W1max + 32.0f + X1 * (127.0f / sxmax)
                           + 0.5f * wn_range / (sx * sw))
                : 2.1e9f;
            mf = fminf(mf, 2.1e9f);
            M = (int)ceilf(mf) + 2;
        }

        // ---- int8 scan, SW-pipelined: prefetch next code row during dp4a ----
        int smax = INT_MIN / 2, thr = INT_MIN / 2;
        int cnt = 0, ovf = 0;
        int candC[CAP], candS[CAP];
        const int4* qp = (const int4*)qw;
        int4 n0 = qp[0], n1 = qp[1], n2 = qp[2], n3 = qp[3];
        qp += 4;
#pragma unroll 2
        for (int code = 0; code < NCODE; code++) {
            const int4 v0 = n0, v1 = n1, v2 = n2, v3 = n3;
            n0 = qp[0]; n1 = qp[1]; n2 = qp[2]; n3 = qp[3];  // pad row at code=511
            qp += 4;
            int a0 = __dp4a(v0.x, qx[0], 0);
            int a1 = __dp4a(v0.y, qx[1], 0);
            int a2 = __dp4a(v0.z, qx[2], 0);
            int a3 = __dp4a(v0.w, qx[3], 0);
            a0 = __dp4a(v1.x, qx[4],  a0); a1 = __dp4a(v1.y, qx[5],  a1);
            a2 = __dp4a(v1.z, qx[6],  a2); a3 = __dp4a(v1.w, qx[7],  a3);
            a0 = __dp4a(v2.x, qx[8],  a0); a1 = __dp4a(v2.y, qx[9],  a1);
            a2 = __dp4a(v2.z, qx[10], a2); a3 = __dp4a(v2.w, qx[11], a3);
            a0 = __dp4a(v3.x, qx[12], a0); a1 = __dp4a(v3.y, qx[13], a1);
            a2 = __dp4a(v3.z, qx[14], a2); a3 = __dp4a(v3.w, qx[15], a3);
            int s = (a0 + a1) + (a2 + a3);
            if (s > thr) {                       // rare path
                if (s > smax) { smax = s; thr = smax - M; }
                if (cnt == CAP) {                // purge entries at/below threshold
                    int nc = 0;
#pragma unroll
                    for (int sl = 0; sl < CAP; sl++)
                        if (candS[sl] > thr) { candS[nc] = candS[sl]; candC[nc] = candC[sl]; nc++; }
                    cnt = nc;
                }
                if (cnt < CAP) { candS[cnt] = s; candC[cnt] = code; cnt++; }
                else ovf = 1;                    // sticky -> exact full rescan
            }
        }

        // ---- exact rescore (R3-identical arithmetic; streamed x/w) ----
        const float4* wq = (const float4*)w;
        float bd = FLT_MAX; int bi = 0;
        if (ovf) {
            for (int code = 0; code < NCODE; code++) {
                float dv = exact_dist(xb, A, wq, wn_s, code);
                if (dv < bd) { bd = dv; bi = code; }   // ascending: first-min
            }
        } else {
            const int fthr = smax - M;
            int live = 0, onlyc = 0;
            for (int e = 0; e < cnt; e++)
                if (candS[e] >= fthr) { live++; onlyc = candC[e]; }
            if (live == 1) {
                bi = onlyc;                            // argmin proven
            } else {
                for (int e = 0; e < cnt; e++) {        // order-preserved: ascending
                    if (candS[e] >= fthr) {
                        float dv = exact_dist(xb, A, wq, wn_s, candC[e]);
                        if (dv < bd) { bd = dv; bi = candC[e]; }  // strict <
                    }
                }
            }
        }

        // ---- epilogue ----
        out_disc[vec] = (float)bi;
        float* qb = out_q + (b << 18) + hw;
#pragma unroll
        for (int i = 0; i < 16; i++) {
            float4 wv = __ldg(&wq[bi * 16 + i]);
            float x0 = xb[(4*i+0) << 12];
            float x1 = xb[(4*i+1) << 12];
            float x2 = xb[(4*i+2) << 12];
            float x3 = xb[(4*i+3) << 12];
            float d0 = wv.x - x0, d1 = wv.y - x1;
            float d2 = wv.z - x2, d3 = wv.w - x3;
            qb[(4*i+0) << 12] = x0 + d0;
            qb[(4*i+1) << 12] = x1 + d1;
            qb[(4*i+2) << 12] = x2 + d2;
            qb[(4*i+3) << 12] = x3 + d3;
            lsum = fmaf(d0, d0, lsum); lsum = fmaf(d1, d1, lsum);
            lsum = fmaf(d2, d2, lsum); lsum = fmaf(d3, d3, lsum);
        }
    }

    // ---- deterministic loss: warp -> block serial -> last block ----
#pragma unroll
    for (int o = 16; o > 0; o >>= 1) lsum += __shfl_xor_sync(~0u, lsum, o);
    __syncthreads();
    if (lane == 0) red[wid] = lsum;
    __syncthreads();
    if (tid == 0) {
        float s = 0.f;
#pragma unroll
        for (int i = 0; i < TPB / 32; i++) s += red[i];
        g_psum[bid] = s;
        __threadfence();
        int a = atomicAdd(&g_ctr, 1);
        if (a == GRIDB - 1) {                  // fixed-order exact final sum
            float t = 0.f;
            for (int i = 0; i < GRIDB; i++) t += g_psum[i];
            float m = t * inv_total;
            out_loss[0] = m + 0.25f * m;
            g_ctr = 0;                         // reset for next graph replay
            __threadfence();
        }
    }
}

extern "C" void kernel_launch(void* const* d_in, const int* in_sizes, int n_in,
                              void* d_out, int out_size)
{
    const float* in = (const float*)d_in[0];   // [32,64,64,64] fp32
    const float* w  = (const float*)d_in[1];   // [512,64] fp32
    const int n_elems = in_sizes[0];           // 8388608
    const int nvec    = n_elems / DIMD;        // 131072

    float* out      = (float*)d_out;
    float* out_disc = out;
    float* out_q    = out + nvec;
    float* out_loss = out + nvec + n_elems;

    static bool attr_set = false;
    if (!attr_set) {
        cudaFuncSetAttribute(vq_dp4a_kernel,
                             cudaFuncAttributeMaxDynamicSharedMemorySize, SMEM_TOTAL);
        attr_set = true;
    }
    vq_dp4a_kernel<<<GRIDB, TPB, SMEM_TOTAL>>>(in, w, out_disc, out_q,
                                               out_loss, 1.0f / (float)n_elems);
}